// round 2
// baseline (speedup 1.0000x reference)
#include <cuda_runtime.h>
#include <math.h>

#define T   4096
#define Dm  1024
#define E   8
#define P   256
#define Hd  4096
#define CLAMP_MAXF 4.605170185988092f

// ---------------- scratch (device globals; no allocations allowed) ----------
__device__ float g_simn[P * E];
__device__ float g_scale;
__device__ int   g_topi[T * 2];
__device__ float g_wk[T * 2];
__device__ float g_wsum[T];
__device__ float g_fracsum[E];
__device__ int   g_usage[E];
__device__ int   g_cnt[E];
__device__ int   g_tok[E * T];
__device__ float g_wt[E * T];
__device__ int   g_slot[T * 2];
__device__ float g_H[(size_t)E * T * Hd];   // 512 MB
__device__ float g_F[(size_t)E * T * Dm];   // 128 MB

// ---------------- k0: normalize sim columns, scale, zero counters -----------
__global__ void k0_prep(const float* __restrict__ sim, const float* __restrict__ temp) {
    int tid = threadIdx.x;
    __shared__ float norms[E];
    if (tid < E) {
        g_fracsum[tid] = 0.f;
        g_usage[tid]   = 0;
        g_cnt[tid]     = 0;
        float s = 0.f;
        for (int p = 0; p < P; p++) { float v = sim[p * E + tid]; s += v * v; }
        norms[tid] = fmaxf(sqrtf(s), 1e-12f);
    }
    if (tid == 0) g_scale = expf(fminf(temp[0], CLAMP_MAXF));
    __syncthreads();
    for (int i = tid; i < P * E; i += blockDim.x)
        g_simn[i] = sim[i] / norms[i % E];
}

// ---------------- k1: fused gate (proj GEMM + cosine logits + softmax + top2)
__global__ __launch_bounds__(256) void k1_gate(const float* __restrict__ x,
                                               const float* __restrict__ Wp,
                                               const float* __restrict__ bp) {
    __shared__ float xs[32][36];      // [d][token], padded
    __shared__ float projS[32][260];  // [token][p]
    __shared__ float simnS[P * E];
    __shared__ float fracS[E];
    __shared__ int   usageS[E];

    int tid = threadIdx.x;
    int t0  = blockIdx.x * 32;

    if (tid < E) { fracS[tid] = 0.f; usageS[tid] = 0; }
    for (int i = tid; i < P * E; i += 256) simnS[i] = g_simn[i];

    float acc[32];
    float bpv = bp[tid];
#pragma unroll
    for (int i = 0; i < 32; i++) acc[i] = bpv;

    for (int d0 = 0; d0 < Dm; d0 += 32) {
        __syncthreads();
        {
            int t = tid >> 3, dg = tid & 7;
            float4 v = *(const float4*)&x[(size_t)(t0 + t) * Dm + d0 + dg * 4];
            xs[dg * 4 + 0][t] = v.x; xs[dg * 4 + 1][t] = v.y;
            xs[dg * 4 + 2][t] = v.z; xs[dg * 4 + 3][t] = v.w;
        }
        __syncthreads();
        const float4* wp4 = (const float4*)&Wp[(size_t)tid * Dm + d0];
#pragma unroll
        for (int dg = 0; dg < 8; dg++) {
            float4 w4 = wp4[dg];
            float wv[4] = {w4.x, w4.y, w4.z, w4.w};
#pragma unroll
            for (int j = 0; j < 4; j++) {
                int d = dg * 4 + j;
#pragma unroll
                for (int tt = 0; tt < 32; tt += 4) {
                    float4 xv = *(const float4*)&xs[d][tt];
                    acc[tt + 0] += wv[j] * xv.x;
                    acc[tt + 1] += wv[j] * xv.y;
                    acc[tt + 2] += wv[j] * xv.z;
                    acc[tt + 3] += wv[j] * xv.w;
                }
            }
        }
    }
#pragma unroll
    for (int i = 0; i < 32; i++) projS[i][tid] = acc[i];
    __syncthreads();

    // 8-lane group per token: t = tid>>3 (0..31), e = tid&7
    int t = tid >> 3, e = tid & 7;

    // row norm
    float s = 0.f;
    for (int p = e; p < P; p += 8) { float v = projS[t][p]; s += v * v; }
    s += __shfl_xor_sync(0xffffffffu, s, 1);
    s += __shfl_xor_sync(0xffffffffu, s, 2);
    s += __shfl_xor_sync(0xffffffffu, s, 4);
    float rnorm = 1.f / fmaxf(sqrtf(s), 1e-12f);

    // logit for expert e
    float lg = 0.f;
    for (int p = 0; p < P; p++) lg += projS[t][p] * simnS[p * E + e];
    lg *= rnorm * g_scale;

    // softmax over 8 lanes
    float m = lg;
    m = fmaxf(m, __shfl_xor_sync(0xffffffffu, m, 1));
    m = fmaxf(m, __shfl_xor_sync(0xffffffffu, m, 2));
    m = fmaxf(m, __shfl_xor_sync(0xffffffffu, m, 4));
    float ex = expf(lg - m);
    float se = ex;
    se += __shfl_xor_sync(0xffffffffu, se, 1);
    se += __shfl_xor_sync(0xffffffffu, se, 2);
    se += __shfl_xor_sync(0xffffffffu, se, 4);
    float prob = ex / se;

    atomicAdd(&fracS[e], prob);

    // top-1 (tie -> lower index)
    float v1 = prob; int i1 = e;
#pragma unroll
    for (int off = 1; off < 8; off <<= 1) {
        float ov = __shfl_xor_sync(0xffffffffu, v1, off);
        int   oi = __shfl_xor_sync(0xffffffffu, i1, off);
        if (ov > v1 || (ov == v1 && oi < i1)) { v1 = ov; i1 = oi; }
    }
    // top-2
    float v2 = (e == i1) ? -1e30f : prob; int i2 = e;
#pragma unroll
    for (int off = 1; off < 8; off <<= 1) {
        float ov = __shfl_xor_sync(0xffffffffu, v2, off);
        int   oi = __shfl_xor_sync(0xffffffffu, i2, off);
        if (ov > v2 || (ov == v2 && oi < i2)) { v2 = ov; i2 = oi; }
    }

    int tg = t0 + t;
    if (e == 0) {
        float denom = v1 + v2 + 1e-8f;
        float w0 = v1 / denom, w1 = v2 / denom;
        g_topi[tg * 2 + 0] = i1;  g_topi[tg * 2 + 1] = i2;
        g_wk[tg * 2 + 0]   = w0;  g_wk[tg * 2 + 1]   = w1;
        g_wsum[tg] = w0 + w1;
        atomicAdd(&usageS[i1], 1);
        atomicAdd(&usageS[i2], 1);
    }
    __syncthreads();
    if (tid < E) {
        atomicAdd(&g_fracsum[tid], fracS[tid]);
        atomicAdd(&g_usage[tid],   usageS[tid]);
    }
}

// ---------------- k2: build per-expert token lists ---------------------------
__global__ void k2_lists() {
    int t = blockIdx.x * blockDim.x + threadIdx.x;
    if (t >= T) return;
#pragma unroll
    for (int k = 0; k < 2; k++) {
        int e = g_topi[t * 2 + k];
        int pos = atomicAdd(&g_cnt[e], 1);
        g_tok[e * T + pos] = t;
        g_wt[e * T + pos]  = g_wk[t * 2 + k];
        g_slot[t * 2 + k]  = pos;
    }
}

// ---------------- k4: H = gather(X) @ A_e^T + a_bias  (per expert) -----------
__global__ __launch_bounds__(256) void k4_gemm1(const float* __restrict__ x,
                                                const float* __restrict__ A,
                                                const float* __restrict__ a_bias) {
    int e = blockIdx.z;
    int n = g_cnt[e];
    int rowBase = blockIdx.y * 64;
    if (rowBase >= n) return;
    int colBase = blockIdx.x * 64;

    __shared__ float Xs[16][68];
    __shared__ float As[16][68];

    int tid = threadIdx.x;
    int li  = tid >> 2;          // 0..63
    int kq  = (tid & 3) * 4;     // 0,4,8,12
    int myTok = (rowBase + li < n) ? g_tok[e * T + rowBase + li] : -1;
    const float* Ab = A + ((size_t)e * Hd + colBase + li) * Dm;

    float acc[4][4];
#pragma unroll
    for (int a = 0; a < 4; a++)
#pragma unroll
        for (int b = 0; b < 4; b++) acc[a][b] = 0.f;

    int ty = tid >> 4, tx = tid & 15;

    for (int k0 = 0; k0 < Dm; k0 += 16) {
        float4 xv = make_float4(0.f, 0.f, 0.f, 0.f);
        if (myTok >= 0) xv = *(const float4*)&x[(size_t)myTok * Dm + k0 + kq];
        float4 av = *(const float4*)&Ab[k0 + kq];
        __syncthreads();
        Xs[kq + 0][li] = xv.x; Xs[kq + 1][li] = xv.y;
        Xs[kq + 2][li] = xv.z; Xs[kq + 3][li] = xv.w;
        As[kq + 0][li] = av.x; As[kq + 1][li] = av.y;
        As[kq + 2][li] = av.z; As[kq + 3][li] = av.w;
        __syncthreads();
#pragma unroll
        for (int k = 0; k < 16; k++) {
            float4 xr = *(const float4*)&Xs[k][ty * 4];
            float4 ar = *(const float4*)&As[k][tx * 4];
            float xa[4] = {xr.x, xr.y, xr.z, xr.w};
            float aa[4] = {ar.x, ar.y, ar.z, ar.w};
#pragma unroll
            for (int a = 0; a < 4; a++)
#pragma unroll
                for (int b = 0; b < 4; b++) acc[a][b] += xa[a] * aa[b];
        }
    }
#pragma unroll
    for (int a = 0; a < 4; a++) {
        int gi = rowBase + ty * 4 + a;
        if (gi < n) {
            const float* bb = &a_bias[(size_t)e * Hd + colBase + tx * 4];
            float4 o;
            o.x = acc[a][0] + bb[0];
            o.y = acc[a][1] + bb[1];
            o.z = acc[a][2] + bb[2];
            o.w = acc[a][3] + bb[3];
            *(float4*)&g_H[((size_t)e * T + gi) * Hd + colBase + tx * 4] = o;
        }
    }
}

// ---------------- k5: F = H @ B_e^T (per expert; bias added in combine) ------
__global__ __launch_bounds__(256) void k5_gemm2(const float* __restrict__ B) {
    int e = blockIdx.z;
    int n = g_cnt[e];
    int rowBase = blockIdx.y * 64;
    if (rowBase >= n) return;
    int colBase = blockIdx.x * 64;

    __shared__ float Hs[16][68];
    __shared__ float Bs[16][68];

    int tid = threadIdx.x;
    int li  = tid >> 2;
    int kq  = (tid & 3) * 4;
    bool rowOk = (rowBase + li < n);
    const float* Hrow = &g_H[((size_t)e * T + (rowOk ? rowBase + li : 0)) * Hd];
    const float* Bb   = B + ((size_t)e * Dm + colBase + li) * Hd;

    float acc[4][4];
#pragma unroll
    for (int a = 0; a < 4; a++)
#pragma unroll
        for (int b = 0; b < 4; b++) acc[a][b] = 0.f;

    int ty = tid >> 4, tx = tid & 15;

    for (int k0 = 0; k0 < Hd; k0 += 16) {
        float4 hv = make_float4(0.f, 0.f, 0.f, 0.f);
        if (rowOk) hv = *(const float4*)&Hrow[k0 + kq];
        float4 bv = *(const float4*)&Bb[k0 + kq];
        __syncthreads();
        Hs[kq + 0][li] = hv.x; Hs[kq + 1][li] = hv.y;
        Hs[kq + 2][li] = hv.z; Hs[kq + 3][li] = hv.w;
        Bs[kq + 0][li] = bv.x; Bs[kq + 1][li] = bv.y;
        Bs[kq + 2][li] = bv.z; Bs[kq + 3][li] = bv.w;
        __syncthreads();
#pragma unroll
        for (int k = 0; k < 16; k++) {
            float4 hr = *(const float4*)&Hs[k][ty * 4];
            float4 br = *(const float4*)&Bs[k][tx * 4];
            float ha[4] = {hr.x, hr.y, hr.z, hr.w};
            float ba[4] = {br.x, br.y, br.z, br.w};
#pragma unroll
            for (int a = 0; a < 4; a++)
#pragma unroll
                for (int b = 0; b < 4; b++) acc[a][b] += ha[a] * ba[b];
        }
    }
#pragma unroll
    for (int a = 0; a < 4; a++) {
        int gi = rowBase + ty * 4 + a;
        if (gi < n) {
            float4 o;
            o.x = acc[a][0]; o.y = acc[a][1]; o.z = acc[a][2]; o.w = acc[a][3];
            *(float4*)&g_F[((size_t)e * T + gi) * Dm + colBase + tx * 4] = o;
        }
    }
}

// ---------------- k7: out = (w0+w1)*x + w0*(f0+bb0) + w1*(f1+bb1) ------------
__global__ __launch_bounds__(256) void k7_combine(const float* __restrict__ x,
                                                  const float* __restrict__ b_bias,
                                                  float* __restrict__ out) {
    int t = blockIdx.x;
    int d = threadIdx.x * 4;
    int e0 = g_topi[t * 2 + 0], e1 = g_topi[t * 2 + 1];
    int s0 = g_slot[t * 2 + 0], s1 = g_slot[t * 2 + 1];
    float w0 = g_wk[t * 2 + 0], w1 = g_wk[t * 2 + 1];
    float ws = g_wsum[t];

    float4 xv  = *(const float4*)&x[(size_t)t * Dm + d];
    float4 f0  = *(const float4*)&g_F[((size_t)e0 * T + s0) * Dm + d];
    float4 f1  = *(const float4*)&g_F[((size_t)e1 * T + s1) * Dm + d];
    float4 bb0 = *(const float4*)&b_bias[(size_t)e0 * Dm + d];
    float4 bb1 = *(const float4*)&b_bias[(size_t)e1 * Dm + d];

    float4 o;
    o.x = ws * xv.x + w0 * (f0.x + bb0.x) + w1 * (f1.x + bb1.x);
    o.y = ws * xv.y + w0 * (f0.y + bb0.y) + w1 * (f1.y + bb1.y);
    o.z = ws * xv.z + w0 * (f0.z + bb0.z) + w1 * (f1.z + bb1.z);
    o.w = ws * xv.w + w0 * (f0.w + bb0.w) + w1 * (f1.w + bb1.w);
    *(float4*)&out[(size_t)t * Dm + d] = o;
}

// ---------------- k6: aux_loss, frac, usage tail -----------------------------
__global__ void k6_tail(float* __restrict__ out) {
    int tid = threadIdx.x;
    __shared__ float frac[E];
    if (tid < E) frac[tid] = g_fracsum[tid] / (float)T;
    __syncthreads();
    if (tid == 0) {
        float aux = 0.f;
        for (int i = 0; i < E; i++) { float df = frac[i] - 1.0f / E; aux += df * df; }
        out[(size_t)T * Dm] = aux;
    }
    if (tid < E) {
        out[(size_t)T * Dm + 1 + tid]     = frac[tid];
        out[(size_t)T * Dm + 1 + E + tid] = (float)g_usage[tid];
    }
}

// ---------------- launch ------------------------------------------------------
extern "C" void kernel_launch(void* const* d_in, const int* in_sizes, int n_in,
                              void* d_out, int out_size) {
    const float* x      = (const float*)d_in[0];
    const float* Wp     = (const float*)d_in[1];
    const float* bp     = (const float*)d_in[2];
    const float* sim    = (const float*)d_in[3];
    const float* temp   = (const float*)d_in[4];
    const float* A      = (const float*)d_in[5];
    const float* a_bias = (const float*)d_in[6];
    const float* Bw     = (const float*)d_in[7];
    const float* b_bias = (const float*)d_in[8];
    float* out = (float*)d_out;

    k0_prep<<<1, 256>>>(sim, temp);
    k1_gate<<<T / 32, 256>>>(x, Wp, bp);
    k2_lists<<<T / 256, 256>>>();
    k4_gemm1<<<dim3(Hd / 64, T / 64, E), 256>>>(x, A, a_bias);
    k5_gemm2<<<dim3(Dm / 64, T / 64, E), 256>>>(Bw);
    k7_combine<<<T, 256>>>(x, b_bias, out);
    k6_tail<<<1, 32>>>(out);
}

// round 6
// speedup vs baseline: 2.2290x; 2.2290x over previous
#include <cuda_runtime.h>
#include <cuda_bf16.h>
#include <math.h>
#include <stdint.h>

#define T   4096
#define Dm  1024
#define E   8
#define P   256
#define Hd  4096
#define CLAMP_MAXF 4.605170185988092f

// ======================= scratch (device globals) ===========================
__device__ float g_simn[P * E];
__device__ float g_scale;
__device__ int   g_topi[T * 2];
__device__ float g_wk[T * 2];
__device__ float g_wsum[T];
__device__ float g_fracsum[E];
__device__ int   g_usage[E];
__device__ int   g_cnt[E];
__device__ int   g_tok[E * T];
__device__ int   g_slot[T * 2];

// concatenated split-bf16 operands (K tripled):
//  X rows:  [Xhi | Xlo | Xhi]   (K = 3*Dm)
//  A rows:  [Ahi | Ahi | Alo]   (K = 3*Dm)
//  H rows:  [Hhi | Hlo | Hhi]   (K = 3*Hd)
//  B rows:  [Bhi | Bhi | Blo]   (K = 3*Hd)
__device__ __nv_bfloat16 g_Xc[(size_t)T * 3 * Dm];
__device__ __nv_bfloat16 g_Ac[(size_t)E * Hd * 3 * Dm];
__device__ __nv_bfloat16 g_Bc[(size_t)E * Dm * 3 * Hd];
__device__ __nv_bfloat16 g_Hc[(size_t)E * T * 3 * Hd];
__device__ float         g_F[(size_t)E * T * Dm];

// ======================= small helpers ======================================
__device__ __forceinline__ uint32_t smem_u32(const void* p) {
    uint32_t a;
    asm("{ .reg .u64 t; cvta.to.shared.u64 t, %1; cvt.u32.u64 %0, t; }" : "=r"(a) : "l"(p));
    return a;
}
__device__ __forceinline__ void cp16(uint32_t s, const void* g) {
    asm volatile("cp.async.cg.shared.global [%0], [%1], 16;" :: "r"(s), "l"(g));
}
__device__ __forceinline__ void ldsm4(uint32_t* r, uint32_t a) {
    asm volatile("ldmatrix.sync.aligned.m8n8.x4.shared.b16 {%0,%1,%2,%3}, [%4];"
        : "=r"(r[0]), "=r"(r[1]), "=r"(r[2]), "=r"(r[3]) : "r"(a));
}
__device__ __forceinline__ void mmaop(float* c, const uint32_t* a, const uint32_t* b) {
    asm volatile("mma.sync.aligned.m16n8k16.row.col.f32.bf16.bf16.f32 "
        "{%0,%1,%2,%3}, {%4,%5,%6,%7}, {%8,%9}, {%0,%1,%2,%3};"
        : "+f"(c[0]), "+f"(c[1]), "+f"(c[2]), "+f"(c[3])
        : "r"(a[0]), "r"(a[1]), "r"(a[2]), "r"(a[3]), "r"(b[0]), "r"(b[1]));
}

// ======================= k0: prep ==========================================
__global__ void k0_prep(const float* __restrict__ sim, const float* __restrict__ temp) {
    int tid = threadIdx.x;
    __shared__ float norms[E];
    if (tid < E) {
        g_fracsum[tid] = 0.f; g_usage[tid] = 0; g_cnt[tid] = 0;
        float s = 0.f;
        for (int p = 0; p < P; p++) { float v = sim[p * E + tid]; s += v * v; }
        norms[tid] = fmaxf(sqrtf(s), 1e-12f);
    }
    if (tid == 0) g_scale = expf(fminf(temp[0], CLAMP_MAXF));
    __syncthreads();
    for (int i = tid; i < P * E; i += blockDim.x)
        g_simn[i] = sim[i] / norms[i % E];
}

// ======================= kconv: fp32 -> concatenated split-bf16 =============
// writes hi at [col], hi at [col+offHi2], lo at [col+offLo] within 3K-wide rows
template<int K>
__global__ __launch_bounds__(256) void kconv(const float4* __restrict__ src,
                                             __nv_bfloat16* __restrict__ dst,
                                             int n4, int offHi2, int offLo) {
    int i = blockIdx.x * 256 + threadIdx.x;
    if (i >= n4) return;
    float4 v = src[i];
    int row = i / (K / 4);
    int col = (i % (K / 4)) * 4;
    float vv[4] = {v.x, v.y, v.z, v.w};
    uint32_t hp[2], lp[2];
#pragma unroll
    for (int q = 0; q < 2; q++) {
        __nv_bfloat16 h0 = __float2bfloat16(vv[2 * q + 0]);
        __nv_bfloat16 h1 = __float2bfloat16(vv[2 * q + 1]);
        __nv_bfloat16 l0 = __float2bfloat16(vv[2 * q + 0] - __bfloat162float(h0));
        __nv_bfloat16 l1 = __float2bfloat16(vv[2 * q + 1] - __bfloat162float(h1));
        hp[q] = (uint32_t)__bfloat16_as_ushort(h0) | ((uint32_t)__bfloat16_as_ushort(h1) << 16);
        lp[q] = (uint32_t)__bfloat16_as_ushort(l0) | ((uint32_t)__bfloat16_as_ushort(l1) << 16);
    }
    size_t base = (size_t)row * (3 * K) + col;
    *(uint2*)&dst[base]          = make_uint2(hp[0], hp[1]);
    *(uint2*)&dst[base + offHi2] = make_uint2(hp[0], hp[1]);
    *(uint2*)&dst[base + offLo]  = make_uint2(lp[0], lp[1]);
}

// ======================= k1: fused gate ====================================
__global__ __launch_bounds__(256) void k1_gate(const float* __restrict__ x,
                                               const float* __restrict__ Wp,
                                               const float* __restrict__ bp) {
    __shared__ float xs[32][36];
    __shared__ float projS[32][260];
    __shared__ float simnS[P * E];
    __shared__ float fracS[E];
    __shared__ int   usageS[E];

    int tid = threadIdx.x;
    int t0  = blockIdx.x * 32;

    if (tid < E) { fracS[tid] = 0.f; usageS[tid] = 0; }
    for (int i = tid; i < P * E; i += 256) simnS[i] = g_simn[i];

    float acc[32];
    float bpv = bp[tid];
#pragma unroll
    for (int i = 0; i < 32; i++) acc[i] = bpv;

    for (int d0 = 0; d0 < Dm; d0 += 32) {
        __syncthreads();
        {
            int t = tid >> 3, dg = tid & 7;
            float4 v = *(const float4*)&x[(size_t)(t0 + t) * Dm + d0 + dg * 4];
            xs[dg * 4 + 0][t] = v.x; xs[dg * 4 + 1][t] = v.y;
            xs[dg * 4 + 2][t] = v.z; xs[dg * 4 + 3][t] = v.w;
        }
        __syncthreads();
        const float4* wp4 = (const float4*)&Wp[(size_t)tid * Dm + d0];
#pragma unroll
        for (int dg = 0; dg < 8; dg++) {
            float4 w4 = wp4[dg];
            float wv[4] = {w4.x, w4.y, w4.z, w4.w};
#pragma unroll
            for (int j = 0; j < 4; j++) {
                int d = dg * 4 + j;
#pragma unroll
                for (int tt = 0; tt < 32; tt += 4) {
                    float4 xv = *(const float4*)&xs[d][tt];
                    acc[tt + 0] += wv[j] * xv.x;
                    acc[tt + 1] += wv[j] * xv.y;
                    acc[tt + 2] += wv[j] * xv.z;
                    acc[tt + 3] += wv[j] * xv.w;
                }
            }
        }
    }
#pragma unroll
    for (int i = 0; i < 32; i++) projS[i][tid] = acc[i];
    __syncthreads();

    int t = tid >> 3, e = tid & 7;

    float s = 0.f;
    for (int p = e; p < P; p += 8) { float v = projS[t][p]; s += v * v; }
    s += __shfl_xor_sync(0xffffffffu, s, 1);
    s += __shfl_xor_sync(0xffffffffu, s, 2);
    s += __shfl_xor_sync(0xffffffffu, s, 4);
    float rnorm = 1.f / fmaxf(sqrtf(s), 1e-12f);

    float lg = 0.f;
    for (int p = 0; p < P; p++) lg += projS[t][p] * simnS[p * E + e];
    lg *= rnorm * g_scale;

    float m = lg;
    m = fmaxf(m, __shfl_xor_sync(0xffffffffu, m, 1));
    m = fmaxf(m, __shfl_xor_sync(0xffffffffu, m, 2));
    m = fmaxf(m, __shfl_xor_sync(0xffffffffu, m, 4));
    float ex = expf(lg - m);
    float se = ex;
    se += __shfl_xor_sync(0xffffffffu, se, 1);
    se += __shfl_xor_sync(0xffffffffu, se, 2);
    se += __shfl_xor_sync(0xffffffffu, se, 4);
    float prob = ex / se;

    atomicAdd(&fracS[e], prob);

    float v1 = prob; int i1 = e;
#pragma unroll
    for (int off = 1; off < 8; off <<= 1) {
        float ov = __shfl_xor_sync(0xffffffffu, v1, off);
        int   oi = __shfl_xor_sync(0xffffffffu, i1, off);
        if (ov > v1 || (ov == v1 && oi < i1)) { v1 = ov; i1 = oi; }
    }
    float v2 = (e == i1) ? -1e30f : prob; int i2 = e;
#pragma unroll
    for (int off = 1; off < 8; off <<= 1) {
        float ov = __shfl_xor_sync(0xffffffffu, v2, off);
        int   oi = __shfl_xor_sync(0xffffffffu, i2, off);
        if (ov > v2 || (ov == v2 && oi < i2)) { v2 = ov; i2 = oi; }
    }

    int tg = t0 + t;
    if (e == 0) {
        float denom = v1 + v2 + 1e-8f;
        float w0 = v1 / denom, w1 = v2 / denom;
        g_topi[tg * 2 + 0] = i1;  g_topi[tg * 2 + 1] = i2;
        g_wk[tg * 2 + 0]   = w0;  g_wk[tg * 2 + 1]   = w1;
        g_wsum[tg] = w0 + w1;
        atomicAdd(&usageS[i1], 1);
        atomicAdd(&usageS[i2], 1);
    }
    __syncthreads();
    if (tid < E) {
        atomicAdd(&g_fracsum[tid], fracS[tid]);
        atomicAdd(&g_usage[tid],   usageS[tid]);
    }
}

// ======================= k2: per-expert token lists =========================
__global__ void k2_lists() {
    int t = blockIdx.x * blockDim.x + threadIdx.x;
    if (t >= T) return;
#pragma unroll
    for (int k = 0; k < 2; k++) {
        int e = g_topi[t * 2 + k];
        int pos = atomicAdd(&g_cnt[e], 1);
        g_tok[e * T + pos] = t;
        g_slot[t * 2 + k]  = pos;
    }
}

// ======================= HMMA GEMM (mma.sync, cp.async 3-stage) =============
// MODE 0: H = gather(Xc) @ Ac^T + a_bias  (Keff=3072) -> split write to g_Hc
// MODE 1: F = Hc @ Bc^T                    (Keff=12288) -> fp32 g_F
#define STAGE_B 20480               // A tile 128x80B + B tile 128x80B
#define SMEM_GEMM (3 * STAGE_B)     // 61440

template<int MODE>
__global__ __launch_bounds__(256) void kgemm(const float* __restrict__ bias) {
    constexpr int KSEG = (MODE == 0) ? Dm : Hd;
    constexpr int KTOT = 3 * KSEG;
    constexpr int NTOT = (MODE == 0) ? Hd : Dm;
    constexpr int NK   = KTOT / 32;

    int e = blockIdx.z;
    int n = g_cnt[e];
    int rowBase = blockIdx.y * 128;
    if (rowBase >= n) return;
    int colBase = blockIdx.x * 128;

    extern __shared__ char sm[];
    uint32_t sb = smem_u32(sm);
    __shared__ int s_tok[128];

    int tid  = threadIdx.x;
    int wid  = tid >> 5, lane = tid & 31;

    if (MODE == 0) {
        if (tid < 128) s_tok[tid] = (rowBase + tid < n) ? g_tok[e * T + rowBase + tid] : 0;
        __syncthreads();
    }

    // -------- cp.async source pointers: each thread owns rows rA, rA+64, chunk cA
    int cA = tid & 3, rA = tid >> 2;
    const __nv_bfloat16 *pa0, *pa1;
    if (MODE == 0) {
        pa0 = g_Xc + (size_t)s_tok[rA]      * KTOT;
        pa1 = g_Xc + (size_t)s_tok[rA + 64] * KTOT;
    } else {
        pa0 = g_Hc + ((size_t)e * T + rowBase + rA)      * KTOT;
        pa1 = g_Hc + ((size_t)e * T + rowBase + rA + 64) * KTOT;
    }
    const __nv_bfloat16* W = (MODE == 0) ? g_Ac : g_Bc;
    const __nv_bfloat16* pb0 = W + ((size_t)e * NTOT + colBase + rA)      * KTOT;
    const __nv_bfloat16* pb1 = W + ((size_t)e * NTOT + colBase + rA + 64) * KTOT;
    const char* qa0 = (const char*)pa0 + cA * 16;
    const char* qa1 = (const char*)pa1 + cA * 16;
    const char* qb0 = (const char*)pb0 + cA * 16;
    const char* qb1 = (const char*)pb1 + cA * 16;
    uint32_t sA0 = (uint32_t)(rA * 80 + cA * 16);
    uint32_t sA1 = sA0 + 64 * 80;
    uint32_t sB0 = 10240 + sA0;
    uint32_t sB1 = 10240 + sA1;

#define ISSUE(st, kt) do {                                    \
    uint32_t s0_ = sb + (uint32_t)(st) * STAGE_B;             \
    int kb_ = (kt) * 64;                                      \
    cp16(s0_ + sA0, qa0 + kb_);  cp16(s0_ + sA1, qa1 + kb_);  \
    cp16(s0_ + sB0, qb0 + kb_);  cp16(s0_ + sB1, qb1 + kb_);  \
    asm volatile("cp.async.commit_group;" ::: "memory");      \
} while (0)

    // -------- fragment smem offsets (80B row pitch: conflict-free ldmatrix)
    int wm = wid >> 2, wn = wid & 3;
    uint32_t aOff[4], bOff[2];
#pragma unroll
    for (int mi = 0; mi < 4; mi++) {
        int r = wm * 64 + mi * 16 + (lane & 15);
        aOff[mi] = (uint32_t)(r * 80 + (lane >> 4) * 16);
    }
#pragma unroll
    for (int bi = 0; bi < 2; bi++) {
        int r = wn * 32 + bi * 16 + (lane & 7) + ((lane >> 4) & 1) * 8;
        bOff[bi] = (uint32_t)(10240 + r * 80 + ((lane >> 3) & 1) * 16);
    }

    float acc[4][4][4];
#pragma unroll
    for (int mi = 0; mi < 4; mi++)
#pragma unroll
        for (int ni = 0; ni < 4; ni++)
#pragma unroll
            for (int q = 0; q < 4; q++) acc[mi][ni][q] = 0.f;

    ISSUE(0, 0);
    ISSUE(1, 1);

#pragma unroll 1
    for (int kt = 0; kt < NK; kt++) {
        asm volatile("cp.async.wait_group 1;" ::: "memory");
        __syncthreads();
        if (kt + 2 < NK) ISSUE((kt + 2) % 3, kt + 2);
        uint32_t stBase = sb + (uint32_t)(kt % 3) * STAGE_B;
#pragma unroll
        for (int ks = 0; ks < 2; ks++) {
            uint32_t a[4][4], b[2][4];
#pragma unroll
            for (int mi = 0; mi < 4; mi++) ldsm4(a[mi], stBase + aOff[mi] + ks * 32);
#pragma unroll
            for (int bi = 0; bi < 2; bi++) ldsm4(b[bi], stBase + bOff[bi] + ks * 32);
#pragma unroll
            for (int mi = 0; mi < 4; mi++) {
                mmaop(acc[mi][0], a[mi], &b[0][0]);
                mmaop(acc[mi][1], a[mi], &b[0][2]);
                mmaop(acc[mi][2], a[mi], &b[1][0]);
                mmaop(acc[mi][3], a[mi], &b[1][2]);
            }
        }
    }
#undef ISSUE

    // -------- epilogue
    int lr = lane >> 2, lc = (lane & 3) * 2;
#pragma unroll
    for (int mi = 0; mi < 4; mi++) {
#pragma unroll
        for (int h = 0; h < 2; h++) {
            int g = rowBase + wm * 64 + mi * 16 + lr + h * 8;
            if (g < n) {
#pragma unroll
                for (int ni = 0; ni < 4; ni++) {
                    int col = colBase + wn * 32 + ni * 8 + lc;
                    float c0 = acc[mi][ni][2 * h + 0];
                    float c1 = acc[mi][ni][2 * h + 1];
                    if (MODE == 0) {
                        float v0 = c0 + bias[(size_t)e * Hd + col];
                        float v1 = c1 + bias[(size_t)e * Hd + col + 1];
                        __nv_bfloat16 h0 = __float2bfloat16(v0);
                        __nv_bfloat16 h1 = __float2bfloat16(v1);
                        __nv_bfloat16 l0 = __float2bfloat16(v0 - __bfloat162float(h0));
                        __nv_bfloat16 l1 = __float2bfloat16(v1 - __bfloat162float(h1));
                        uint32_t hp = (uint32_t)__bfloat16_as_ushort(h0) | ((uint32_t)__bfloat16_as_ushort(h1) << 16);
                        uint32_t lp = (uint32_t)__bfloat16_as_ushort(l0) | ((uint32_t)__bfloat16_as_ushort(l1) << 16);
                        size_t base = ((size_t)e * T + g) * (3 * Hd) + col;
                        *(uint32_t*)&g_Hc[base]          = hp;
                        *(uint32_t*)&g_Hc[base + Hd]     = lp;
                        *(uint32_t*)&g_Hc[base + 2 * Hd] = hp;
                    } else {
                        size_t base = ((size_t)e * T + g) * Dm + col;
                        *(float2*)&g_F[base] = make_float2(c0, c1);
                    }
                }
            }
        }
    }
}

// ======================= k7: combine ========================================
__global__ __launch_bounds__(256) void k7_combine(const float* __restrict__ x,
                                                  const float* __restrict__ b_bias,
                                                  float* __restrict__ out) {
    int t = blockIdx.x;
    int d = threadIdx.x * 4;
    int e0 = g_topi[t * 2 + 0], e1 = g_topi[t * 2 + 1];
    int s0 = g_slot[t * 2 + 0], s1 = g_slot[t * 2 + 1];
    float w0 = g_wk[t * 2 + 0], w1 = g_wk[t * 2 + 1];
    float ws = g_wsum[t];

    float4 xv  = *(const float4*)&x[(size_t)t * Dm + d];
    float4 f0  = *(const float4*)&g_F[((size_t)e0 * T + s0) * Dm + d];
    float4 f1  = *(const float4*)&g_F[((size_t)e1 * T + s1) * Dm + d];
    float4 bb0 = *(const float4*)&b_bias[(size_t)e0 * Dm + d];
    float4 bb1 = *(const float4*)&b_bias[(size_t)e1 * Dm + d];

    float4 o;
    o.x = ws * xv.x + w0 * (f0.x + bb0.x) + w1 * (f1.x + bb1.x);
    o.y = ws * xv.y + w0 * (f0.y + bb0.y) + w1 * (f1.y + bb1.y);
    o.z = ws * xv.z + w0 * (f0.z + bb0.z) + w1 * (f1.z + bb1.z);
    o.w = ws * xv.w + w0 * (f0.w + bb0.w) + w1 * (f1.w + bb1.w);
    *(float4*)&out[(size_t)t * Dm + d] = o;
}

// ======================= k6: tail ===========================================
__global__ void k6_tail(float* __restrict__ out) {
    int tid = threadIdx.x;
    __shared__ float frac[E];
    if (tid < E) frac[tid] = g_fracsum[tid] / (float)T;
    __syncthreads();
    if (tid == 0) {
        float aux = 0.f;
        for (int i = 0; i < E; i++) { float df = frac[i] - 1.0f / E; aux += df * df; }
        out[(size_t)T * Dm] = aux;
    }
    if (tid < E) {
        out[(size_t)T * Dm + 1 + tid]     = frac[tid];
        out[(size_t)T * Dm + 1 + E + tid] = (float)g_usage[tid];
    }
}

// ======================= launch =============================================
extern "C" void kernel_launch(void* const* d_in, const int* in_sizes, int n_in,
                              void* d_out, int out_size) {
    const float* x      = (const float*)d_in[0];
    const float* Wp     = (const float*)d_in[1];
    const float* bp     = (const float*)d_in[2];
    const float* sim    = (const float*)d_in[3];
    const float* temp   = (const float*)d_in[4];
    const float* A      = (const float*)d_in[5];
    const float* a_bias = (const float*)d_in[6];
    const float* Bw     = (const float*)d_in[7];
    const float* b_bias = (const float*)d_in[8];
    float* out = (float*)d_out;

    cudaFuncSetAttribute((const void*)kgemm<0>, cudaFuncAttributeMaxDynamicSharedMemorySize, SMEM_GEMM);
    cudaFuncSetAttribute((const void*)kgemm<1>, cudaFuncAttributeMaxDynamicSharedMemorySize, SMEM_GEMM);

    __nv_bfloat16* xc = nullptr; __nv_bfloat16* ac = nullptr; __nv_bfloat16* bc = nullptr;
    cudaGetSymbolAddress((void**)&xc, g_Xc);
    cudaGetSymbolAddress((void**)&ac, g_Ac);
    cudaGetSymbolAddress((void**)&bc, g_Bc);

    k0_prep<<<1, 256>>>(sim, temp);
    kconv<Dm><<<(T * Dm / 4 + 255) / 256, 256>>>((const float4*)x,  xc, T * Dm / 4,      2 * Dm, Dm);
    kconv<Dm><<<(E * Hd * Dm / 4 + 255) / 256, 256>>>((const float4*)A,  ac, E * Hd * Dm / 4, Dm, 2 * Dm);
    kconv<Hd><<<(E * Dm * Hd / 4 + 255) / 256, 256>>>((const float4*)Bw, bc, E * Dm * Hd / 4, Hd, 2 * Hd);
    k1_gate<<<T / 32, 256>>>(x, Wp, bp);
    k2_lists<<<T / 256, 256>>>();
    kgemm<0><<<dim3(Hd / 128, T / 128, E), 256, SMEM_GEMM>>>(a_bias);
    kgemm<1><<<dim3(Dm / 128, T / 128, E), 256, SMEM_GEMM>>>(nullptr);
    k7_combine<<<T, 256>>>(x, b_bias, out);
    k6_tail<<<1, 32>>>(out);
}

// round 9
// speedup vs baseline: 3.1362x; 1.4070x over previous
#include <cuda_runtime.h>
#include <cuda_bf16.h>
#include <math.h>
#include <stdint.h>

#define T   4096
#define Dm  1024
#define E   8
#define P   256
#define Hd  4096
#define CLAMP_MAXF 4.605170185988092f

// ======================= scratch (device globals) ===========================
__device__ float g_simn[P * E];
__device__ float g_scale;
__device__ int   g_topi[T * 2];
__device__ float g_wk[T * 2];
__device__ float g_wsum[T];
__device__ float g_fracsum[E];
__device__ int   g_usage[E];
__device__ int   g_cnt[E];
__device__ int   g_tok[E * T];
__device__ int   g_slot[T * 2];

// merged hi|lo split-bf16 arrays: hi at [0], lo at [+LO]
#define XLO ((size_t)T * Dm)
#define ALO ((size_t)E * Hd * Dm)
#define BLO ((size_t)E * Dm * Hd)
#define HLO ((size_t)E * T * Hd)
__device__ __nv_bfloat16 g_X2[2 * XLO];
__device__ __nv_bfloat16 g_A2[2 * ALO];
__device__ __nv_bfloat16 g_B2[2 * BLO];
__device__ __nv_bfloat16 g_H2[2 * HLO];
__device__ float         g_F[(size_t)E * T * Dm];

// ======================= small helpers ======================================
__device__ __forceinline__ uint32_t smem_u32(const void* p) {
    uint32_t a;
    asm("{ .reg .u64 t; cvta.to.shared.u64 t, %1; cvt.u32.u64 %0, t; }" : "=r"(a) : "l"(p));
    return a;
}
__device__ __forceinline__ void cp16(uint32_t s, const void* g) {
    asm volatile("cp.async.cg.shared.global [%0], [%1], 16;" :: "r"(s), "l"(g));
}
__device__ __forceinline__ void ldsm4(uint32_t* r, uint32_t a) {
    asm volatile("ldmatrix.sync.aligned.m8n8.x4.shared.b16 {%0,%1,%2,%3}, [%4];"
        : "=r"(r[0]), "=r"(r[1]), "=r"(r[2]), "=r"(r[3]) : "r"(a));
}
__device__ __forceinline__ void mmaop(float* c, const uint32_t* a, const uint32_t* b) {
    asm volatile("mma.sync.aligned.m16n8k16.row.col.f32.bf16.bf16.f32 "
        "{%0,%1,%2,%3}, {%4,%5,%6,%7}, {%8,%9}, {%0,%1,%2,%3};"
        : "+f"(c[0]), "+f"(c[1]), "+f"(c[2]), "+f"(c[3])
        : "r"(a[0]), "r"(a[1]), "r"(a[2]), "r"(a[3]), "r"(b[0]), "r"(b[1]));
}
// XOR swizzle inside an 8KB (128 rows x 64B) tile: conflict-free cp.async + ldmatrix
__device__ __forceinline__ uint32_t swz(uint32_t r, uint32_t ch) {
    uint32_t R = r >> 1;
    uint32_t c8 = (((r & 1u) << 2) | ch) ^ (R & 7u);
    return R * 128u + c8 * 16u;
}

// ======================= k0: prep ==========================================
__global__ void k0_prep(const float* __restrict__ sim, const float* __restrict__ temp) {
    int tid = threadIdx.x;
    __shared__ float norms[E];
    if (tid < E) {
        g_fracsum[tid] = 0.f; g_usage[tid] = 0; g_cnt[tid] = 0;
        float s = 0.f;
        for (int p = 0; p < P; p++) { float v = sim[p * E + tid]; s += v * v; }
        norms[tid] = fmaxf(sqrtf(s), 1e-12f);
    }
    if (tid == 0) g_scale = expf(fminf(temp[0], CLAMP_MAXF));
    __syncthreads();
    for (int i = tid; i < P * E; i += blockDim.x)
        g_simn[i] = sim[i] / norms[i % E];
}

// ======================= ksplit: fp32 -> hi/lo bf16 =========================
__global__ __launch_bounds__(256) void ksplit(const float4* __restrict__ src,
                                              __nv_bfloat16* __restrict__ dst,
                                              size_t loOff, int n4) {
    int i = blockIdx.x * 256 + threadIdx.x;
    if (i >= n4) return;
    float4 v = src[i];
    float vv[4] = {v.x, v.y, v.z, v.w};
    uint32_t hp[2], lp[2];
#pragma unroll
    for (int q = 0; q < 2; q++) {
        __nv_bfloat16 h0 = __float2bfloat16(vv[2 * q + 0]);
        __nv_bfloat16 h1 = __float2bfloat16(vv[2 * q + 1]);
        __nv_bfloat16 l0 = __float2bfloat16(vv[2 * q + 0] - __bfloat162float(h0));
        __nv_bfloat16 l1 = __float2bfloat16(vv[2 * q + 1] - __bfloat162float(h1));
        hp[q] = (uint32_t)__bfloat16_as_ushort(h0) | ((uint32_t)__bfloat16_as_ushort(h1) << 16);
        lp[q] = (uint32_t)__bfloat16_as_ushort(l0) | ((uint32_t)__bfloat16_as_ushort(l1) << 16);
    }
    *(uint2*)&dst[(size_t)i * 4]         = make_uint2(hp[0], hp[1]);
    *(uint2*)&dst[(size_t)i * 4 + loOff] = make_uint2(lp[0], lp[1]);
}

// ======================= k1: fused gate ====================================
__global__ __launch_bounds__(256) void k1_gate(const float* __restrict__ x,
                                               const float* __restrict__ Wp,
                                               const float* __restrict__ bp) {
    __shared__ float xs[32][36];
    __shared__ float projS[32][260];
    __shared__ float simnS[P * E];
    __shared__ float fracS[E];
    __shared__ int   usageS[E];

    int tid = threadIdx.x;
    int t0  = blockIdx.x * 32;

    if (tid < E) { fracS[tid] = 0.f; usageS[tid] = 0; }
    for (int i = tid; i < P * E; i += 256) simnS[i] = g_simn[i];

    float acc[32];
    float bpv = bp[tid];
#pragma unroll
    for (int i = 0; i < 32; i++) acc[i] = bpv;

    for (int d0 = 0; d0 < Dm; d0 += 32) {
        __syncthreads();
        {
            int t = tid >> 3, dg = tid & 7;
            float4 v = *(const float4*)&x[(size_t)(t0 + t) * Dm + d0 + dg * 4];
            xs[dg * 4 + 0][t] = v.x; xs[dg * 4 + 1][t] = v.y;
            xs[dg * 4 + 2][t] = v.z; xs[dg * 4 + 3][t] = v.w;
        }
        __syncthreads();
        const float4* wp4 = (const float4*)&Wp[(size_t)tid * Dm + d0];
#pragma unroll
        for (int dg = 0; dg < 8; dg++) {
            float4 w4 = wp4[dg];
            float wv[4] = {w4.x, w4.y, w4.z, w4.w};
#pragma unroll
            for (int j = 0; j < 4; j++) {
                int d = dg * 4 + j;
#pragma unroll
                for (int tt = 0; tt < 32; tt += 4) {
                    float4 xv = *(const float4*)&xs[d][tt];
                    acc[tt + 0] += wv[j] * xv.x;
                    acc[tt + 1] += wv[j] * xv.y;
                    acc[tt + 2] += wv[j] * xv.z;
                    acc[tt + 3] += wv[j] * xv.w;
                }
            }
        }
    }
#pragma unroll
    for (int i = 0; i < 32; i++) projS[i][tid] = acc[i];
    __syncthreads();

    int t = tid >> 3, e = tid & 7;

    float s = 0.f;
    for (int p = e; p < P; p += 8) { float v = projS[t][p]; s += v * v; }
    s += __shfl_xor_sync(0xffffffffu, s, 1);
    s += __shfl_xor_sync(0xffffffffu, s, 2);
    s += __shfl_xor_sync(0xffffffffu, s, 4);
    float rnorm = 1.f / fmaxf(sqrtf(s), 1e-12f);

    float lg = 0.f;
    for (int p = 0; p < P; p++) lg += projS[t][p] * simnS[p * E + e];
    lg *= rnorm * g_scale;

    float m = lg;
    m = fmaxf(m, __shfl_xor_sync(0xffffffffu, m, 1));
    m = fmaxf(m, __shfl_xor_sync(0xffffffffu, m, 2));
    m = fmaxf(m, __shfl_xor_sync(0xffffffffu, m, 4));
    float ex = expf(lg - m);
    float se = ex;
    se += __shfl_xor_sync(0xffffffffu, se, 1);
    se += __shfl_xor_sync(0xffffffffu, se, 2);
    se += __shfl_xor_sync(0xffffffffu, se, 4);
    float prob = ex / se;

    atomicAdd(&fracS[e], prob);

    float v1 = prob; int i1 = e;
#pragma unroll
    for (int off = 1; off < 8; off <<= 1) {
        float ov = __shfl_xor_sync(0xffffffffu, v1, off);
        int   oi = __shfl_xor_sync(0xffffffffu, i1, off);
        if (ov > v1 || (ov == v1 && oi < i1)) { v1 = ov; i1 = oi; }
    }
    float v2 = (e == i1) ? -1e30f : prob; int i2 = e;
#pragma unroll
    for (int off = 1; off < 8; off <<= 1) {
        float ov = __shfl_xor_sync(0xffffffffu, v2, off);
        int   oi = __shfl_xor_sync(0xffffffffu, i2, off);
        if (ov > v2 || (ov == v2 && oi < i2)) { v2 = ov; i2 = oi; }
    }

    int tg = t0 + t;
    if (e == 0) {
        float denom = v1 + v2 + 1e-8f;
        float w0 = v1 / denom, w1 = v2 / denom;
        g_topi[tg * 2 + 0] = i1;  g_topi[tg * 2 + 1] = i2;
        g_wk[tg * 2 + 0]   = w0;  g_wk[tg * 2 + 1]   = w1;
        g_wsum[tg] = w0 + w1;
        atomicAdd(&usageS[i1], 1);
        atomicAdd(&usageS[i2], 1);
    }
    __syncthreads();
    if (tid < E) {
        atomicAdd(&g_fracsum[tid], fracS[tid]);
        atomicAdd(&g_usage[tid],   usageS[tid]);
    }
}

// ======================= k2: per-expert token lists =========================
__global__ void k2_lists() {
    int t = blockIdx.x * blockDim.x + threadIdx.x;
    if (t >= T) return;
#pragma unroll
    for (int k = 0; k < 2; k++) {
        int e = g_topi[t * 2 + k];
        int pos = atomicAdd(&g_cnt[e], 1);
        g_tok[e * T + pos] = t;
        g_slot[t * 2 + k]  = pos;
    }
}

// ======================= split-reuse 3-term bf16 HMMA GEMM ==================
// MODE 0: H = gather(X) @ A_e^T + a_bias  (K=1024) -> hi/lo bf16 g_H2
// MODE 1: F = H @ B_e^T                    (K=4096) -> fp32 g_F
// per stage: Ah @0, Al @8192, Bh @16384, Bl @24576 (each 128x32 bf16 swizzled)
#define BK 32
#define STAGE_B 32768
#define SMEM_GEMM (3 * STAGE_B)   // 98304

template<int MODE>
__global__ __launch_bounds__(256, 2) void kgemm(const float* __restrict__ bias) {
    constexpr int KTOT = (MODE == 0) ? Dm : Hd;
    constexpr int NTOT = (MODE == 0) ? Hd : Dm;
    constexpr int NK   = KTOT / BK;
    constexpr size_t LOA = (MODE == 0) ? XLO : HLO;
    constexpr size_t LOB = (MODE == 0) ? ALO : BLO;

    int e = blockIdx.z;
    int n = g_cnt[e];
    int rowBase = blockIdx.y * 128;
    if (rowBase >= n) return;
    int colBase = blockIdx.x * 128;

    extern __shared__ char smx[];
    uint32_t sb = smem_u32(smx);
    __shared__ int s_tok[128];

    int tid = threadIdx.x, wid = tid >> 5, lane = tid & 31;

    if (MODE == 0) {
        if (tid < 128) s_tok[tid] = (rowBase + tid < n) ? g_tok[e * T + rowBase + tid] : 0;
        __syncthreads();
    }

    int c = tid & 3, r0 = tid >> 2;
    const __nv_bfloat16* Asrc = (MODE == 0) ? g_X2 : g_H2;
    const __nv_bfloat16* Bsrc = (MODE == 0) ? g_A2 : g_B2;

    size_t aoff0, aoff1;
    if (MODE == 0) {
        aoff0 = (size_t)s_tok[r0] * KTOT;
        aoff1 = (size_t)s_tok[r0 + 64] * KTOT;
    } else {
        aoff0 = ((size_t)e * T + rowBase + r0) * KTOT;
        aoff1 = aoff0 + (size_t)64 * KTOT;
    }
    size_t boff0 = ((size_t)e * NTOT + colBase + r0) * KTOT;
    size_t boff1 = boff0 + (size_t)64 * KTOT;

    const char* qah0 = (const char*)(Asrc + aoff0) + c * 16;
    const char* qah1 = (const char*)(Asrc + aoff1) + c * 16;
    const char* qal0 = (const char*)(Asrc + aoff0 + LOA) + c * 16;
    const char* qal1 = (const char*)(Asrc + aoff1 + LOA) + c * 16;
    const char* qbh0 = (const char*)(Bsrc + boff0) + c * 16;
    const char* qbh1 = (const char*)(Bsrc + boff1) + c * 16;
    const char* qbl0 = (const char*)(Bsrc + boff0 + LOB) + c * 16;
    const char* qbl1 = (const char*)(Bsrc + boff1 + LOB) + c * 16;

    uint32_t so = swz((uint32_t)r0, (uint32_t)c);

#define ISSUE(st, kt) do {                                         \
    uint32_t s0_ = sb + (uint32_t)(st) * STAGE_B;                  \
    size_t kb_ = (size_t)(kt) * (BK * 2);                          \
    cp16(s0_ + so,          qah0 + kb_);                           \
    cp16(s0_ + so + 4096,   qah1 + kb_);                           \
    cp16(s0_ + so + 8192,   qal0 + kb_);                           \
    cp16(s0_ + so + 12288,  qal1 + kb_);                           \
    cp16(s0_ + so + 16384,  qbh0 + kb_);                           \
    cp16(s0_ + so + 20480,  qbh1 + kb_);                           \
    cp16(s0_ + so + 24576,  qbl0 + kb_);                           \
    cp16(s0_ + so + 28672,  qbl1 + kb_);                           \
    asm volatile("cp.async.commit_group;" ::: "memory");           \
} while (0)

    int wm = wid >> 2, wn = wid & 3;
    uint32_t offA[2][4], offB[2][2];
#pragma unroll
    for (int ks = 0; ks < 2; ks++) {
#pragma unroll
        for (int mi = 0; mi < 4; mi++)
            offA[ks][mi] = swz((uint32_t)(wm * 64 + mi * 16 + (lane & 15)),
                               (uint32_t)((lane >> 4) + ks * 2));
#pragma unroll
        for (int bi = 0; bi < 2; bi++)
            offB[ks][bi] = swz((uint32_t)(wn * 32 + bi * 16 + (lane & 7) + ((lane >> 4) & 1) * 8),
                               (uint32_t)(((lane >> 3) & 1) + ks * 2));
    }

    float acc[4][4][4];
#pragma unroll
    for (int mi = 0; mi < 4; mi++)
#pragma unroll
        for (int ni = 0; ni < 4; ni++)
#pragma unroll
            for (int q = 0; q < 4; q++) acc[mi][ni][q] = 0.f;

    ISSUE(0, 0);
    ISSUE(1, 1);

#pragma unroll 1
    for (int kt = 0; kt < NK; kt++) {
        asm volatile("cp.async.wait_group 1;" ::: "memory");
        __syncthreads();
        if (kt + 2 < NK) ISSUE((kt + 2) % 3, kt + 2);
        uint32_t stB = sb + (uint32_t)(kt % 3) * STAGE_B;
#pragma unroll
        for (int ks = 0; ks < 2; ks++) {
            uint32_t a[4][4], bh[2][4], bl[2][4];
#pragma unroll
            for (int mi = 0; mi < 4; mi++) ldsm4(a[mi], stB + offA[ks][mi]);          // Ah
#pragma unroll
            for (int bi = 0; bi < 2; bi++) ldsm4(bh[bi], stB + 16384 + offB[ks][bi]); // Bh
#pragma unroll
            for (int bi = 0; bi < 2; bi++) ldsm4(bl[bi], stB + 24576 + offB[ks][bi]); // Bl
#pragma unroll
            for (int mi = 0; mi < 4; mi++) {          // Ah*Bh + Ah*Bl
                mmaop(acc[mi][0], a[mi], &bh[0][0]);
                mmaop(acc[mi][1], a[mi], &bh[0][2]);
                mmaop(acc[mi][2], a[mi], &bh[1][0]);
                mmaop(acc[mi][3], a[mi], &bh[1][2]);
                mmaop(acc[mi][0], a[mi], &bl[0][0]);
                mmaop(acc[mi][1], a[mi], &bl[0][2]);
                mmaop(acc[mi][2], a[mi], &bl[1][0]);
                mmaop(acc[mi][3], a[mi], &bl[1][2]);
            }
#pragma unroll
            for (int mi = 0; mi < 4; mi++) ldsm4(a[mi], stB + 8192 + offA[ks][mi]);   // Al
#pragma unroll
            for (int mi = 0; mi < 4; mi++) {          // Al*Bh
                mmaop(acc[mi][0], a[mi], &bh[0][0]);
                mmaop(acc[mi][1], a[mi], &bh[0][2]);
                mmaop(acc[mi][2], a[mi], &bh[1][0]);
                mmaop(acc[mi][3], a[mi], &bh[1][2]);
            }
        }
    }
#undef ISSUE

    // -------- epilogue
    int lr = lane >> 2, lc = (lane & 3) * 2;
#pragma unroll
    for (int mi = 0; mi < 4; mi++) {
#pragma unroll
        for (int h = 0; h < 2; h++) {
            int g = rowBase + wm * 64 + mi * 16 + lr + h * 8;
            if (g < n) {
#pragma unroll
                for (int ni = 0; ni < 4; ni++) {
                    int col = colBase + wn * 32 + ni * 8 + lc;
                    float c0 = acc[mi][ni][2 * h + 0];
                    float c1 = acc[mi][ni][2 * h + 1];
                    if (MODE == 0) {
                        float v0 = c0 + bias[(size_t)e * Hd + col];
                        float v1 = c1 + bias[(size_t)e * Hd + col + 1];
                        __nv_bfloat16 h0 = __float2bfloat16(v0);
                        __nv_bfloat16 h1 = __float2bfloat16(v1);
                        __nv_bfloat16 l0 = __float2bfloat16(v0 - __bfloat162float(h0));
                        __nv_bfloat16 l1 = __float2bfloat16(v1 - __bfloat162float(h1));
                        uint32_t hp = (uint32_t)__bfloat16_as_ushort(h0) | ((uint32_t)__bfloat16_as_ushort(h1) << 16);
                        uint32_t lp = (uint32_t)__bfloat16_as_ushort(l0) | ((uint32_t)__bfloat16_as_ushort(l1) << 16);
                        size_t base = ((size_t)e * T + g) * Hd + col;
                        *(uint32_t*)&g_H2[base]       = hp;
                        *(uint32_t*)&g_H2[base + HLO] = lp;
                    } else {
                        size_t base = ((size_t)e * T + g) * Dm + col;
                        *(float2*)&g_F[base] = make_float2(c0, c1);
                    }
                }
            }
        }
    }
}

// ======================= k7: combine ========================================
__global__ __launch_bounds__(256) void k7_combine(const float* __restrict__ x,
                                                  const float* __restrict__ b_bias,
                                                  float* __restrict__ out) {
    int t = blockIdx.x;
    int d = threadIdx.x * 4;
    int e0 = g_topi[t * 2 + 0], e1 = g_topi[t * 2 + 1];
    int s0 = g_slot[t * 2 + 0], s1 = g_slot[t * 2 + 1];
    float w0 = g_wk[t * 2 + 0], w1 = g_wk[t * 2 + 1];
    float ws = g_wsum[t];

    float4 xv  = *(const float4*)&x[(size_t)t * Dm + d];
    float4 f0  = *(const float4*)&g_F[((size_t)e0 * T + s0) * Dm + d];
    float4 f1  = *(const float4*)&g_F[((size_t)e1 * T + s1) * Dm + d];
    float4 bb0 = *(const float4*)&b_bias[(size_t)e0 * Dm + d];
    float4 bb1 = *(const float4*)&b_bias[(size_t)e1 * Dm + d];

    float4 o;
    o.x = ws * xv.x + w0 * (f0.x + bb0.x) + w1 * (f1.x + bb1.x);
    o.y = ws * xv.y + w0 * (f0.y + bb0.y) + w1 * (f1.y + bb1.y);
    o.z = ws * xv.z + w0 * (f0.z + bb0.z) + w1 * (f1.z + bb1.z);
    o.w = ws * xv.w + w0 * (f0.w + bb0.w) + w1 * (f1.w + bb1.w);
    *(float4*)&out[(size_t)t * Dm + d] = o;
}

// ======================= k6: tail ===========================================
__global__ void k6_tail(float* __restrict__ out) {
    int tid = threadIdx.x;
    __shared__ float frac[E];
    if (tid < E) frac[tid] = g_fracsum[tid] / (float)T;
    __syncthreads();
    if (tid == 0) {
        float aux = 0.f;
        for (int i = 0; i < E; i++) { float df = frac[i] - 1.0f / E; aux += df * df; }
        out[(size_t)T * Dm] = aux;
    }
    if (tid < E) {
        out[(size_t)T * Dm + 1 + tid]     = frac[tid];
        out[(size_t)T * Dm + 1 + E + tid] = (float)g_usage[tid];
    }
}

// ======================= launch =============================================
extern "C" void kernel_launch(void* const* d_in, const int* in_sizes, int n_in,
                              void* d_out, int out_size) {
    const float* x      = (const float*)d_in[0];
    const float* Wp     = (const float*)d_in[1];
    const float* bp     = (const float*)d_in[2];
    const float* sim    = (const float*)d_in[3];
    const float* temp   = (const float*)d_in[4];
    const float* A      = (const float*)d_in[5];
    const float* a_bias = (const float*)d_in[6];
    const float* Bw     = (const float*)d_in[7];
    const float* b_bias = (const float*)d_in[8];
    float* out = (float*)d_out;

    cudaFuncSetAttribute((const void*)kgemm<0>, cudaFuncAttributeMaxDynamicSharedMemorySize, SMEM_GEMM);
    cudaFuncSetAttribute((const void*)kgemm<1>, cudaFuncAttributeMaxDynamicSharedMemorySize, SMEM_GEMM);

    __nv_bfloat16 *xp = nullptr, *ap = nullptr, *bp2 = nullptr;
    cudaGetSymbolAddress((void**)&xp,  g_X2);
    cudaGetSymbolAddress((void**)&ap,  g_A2);
    cudaGetSymbolAddress((void**)&bp2, g_B2);

    k0_prep<<<1, 256>>>(sim, temp);
    ksplit<<<T * Dm / 4 / 256, 256>>>((const float4*)x,  xp,  XLO, T * Dm / 4);
    ksplit<<<E * Hd * Dm / 4 / 256, 256>>>((const float4*)A,  ap,  ALO, E * Hd * Dm / 4);
    ksplit<<<E * Dm * Hd / 4 / 256, 256>>>((const float4*)Bw, bp2, BLO, E * Dm * Hd / 4);
    k1_gate<<<T / 32, 256>>>(x, Wp, bp);
    k2_lists<<<T / 256, 256>>>();
    kgemm<0><<<dim3(Hd / 128, T / 128, E), 256, SMEM_GEMM>>>(a_bias);
    kgemm<1><<<dim3(Dm / 128, T / 128, E), 256, SMEM_GEMM>>>(nullptr);
    k7_combine<<<T, 256>>>(x, b_bias, out);
    k6_tail<<<1, 32>>>(out);
}